// round 17
// baseline (speedup 1.0000x reference)
#include <cuda_runtime.h>

#define NQ 9
#define KK 3
#define S 16
#define H 128
#define B 16
#define D 512
#define NTH 512
#define SMEM_CHUNKS 20   // WhhT chunks resident in smem

// scratch (static __device__ — no allocation)
__device__ float2 g_rhoq[S * B * NQ * 4];     // [t][b][n][r*2+c]
__device__ float2 g_A[B * S * 256];           // kron of qubits 0..3 (16x16)
__device__ float2 g_Bm[B * S * 1024];         // kron of qubits 4..8 (32x32)
// transposed weights: [chunk][row] so thread=row loads are coalesced
__device__ ulonglong2 g_WhhT[32 * 512];       // Whh row r, 16B chunk k4 -> [k4*512 + r]
__device__ ulonglong2 g_WihT[9 * 512];        // Wih row r, 16B chunk k  -> [k*512 + r]

__device__ __forceinline__ float2 cmul(float2 a, float2 b) {
    return make_float2(a.x * b.x - a.y * b.y, a.x * b.y + a.y * b.x);
}
__device__ __forceinline__ float sigmoidf_(float x) { return 1.0f / (1.0f + expf(-x)); }

// packed f32x2 FMA (SASS FFMA2; PTX-only per sm_103a)
__device__ __forceinline__ void fma2(unsigned long long &acc,
                                     unsigned long long a, unsigned long long b) {
    asm("fma.rn.f32x2 %0, %1, %2, %3;" : "=l"(acc) : "l"(a), "l"(b), "l"(acc));
}
__device__ __forceinline__ float2 unpack2(unsigned long long v) {
    float lo, hi;
    asm("mov.b64 {%0, %1}, %2;" : "=f"(lo), "=f"(hi) : "l"(v));
    return make_float2(lo, hi);
}
__device__ __forceinline__ unsigned long long pack2(float lo, float hi) {
    unsigned long long v;
    asm("mov.b64 %0, {%1, %2};" : "=l"(v) : "f"(lo), "f"(hi));
    return v;
}

// ---- k_seq dynamic smem layout (float offsets) ----
#define F_WHHS  0                   // 20*512*4 = 40960 floats (WhhT chunks 0..19, [k][r])
#define F_WP    40960               // 27*132 = 3564
#define F_PSI0  44524               // 512 float2 = 1024
#define F_EXCH  45548               // 2*512 float2 = 2048
#define F_G     47596               // 512
#define F_BSUM  48108               // 512
#define F_H     48620               // 128 (16B aligned)
#define F_C     48748               // 128
#define F_X     48876               // 40 (16B aligned)
#define F_AMPS  48916               // 28
#define F_LOG   48944               // 28
#define F_RED   48972               // 192
#define F_NORM  49164               // 12
#define F_NN0   49176               // 4
#define SMEM_FLOATS 49180           // 196,720 bytes (< 232,448 opt-in limit)

// ---------------------------------------------------------------------------
// Kernel 0: transpose weights into [chunk][row] layout.
// ---------------------------------------------------------------------------
__global__ void __launch_bounds__(256) k_transpose(
    const float* __restrict__ Whh, const float* __restrict__ Wih)
{
    int idx = blockIdx.x * 256 + threadIdx.x;
    if (idx < 32 * 512) {
        int k4 = idx >> 9, r = idx & 511;
        g_WhhT[idx] = __ldg((const ulonglong2*)Whh + r * 32 + k4);
    }
    int j = idx - 32 * 512;
    if (j >= 0 && j < 9 * 512) {
        int k = j >> 9, r = j & 511;
        g_WihT[j] = __ldg((const ulonglong2*)Wih + r * 9 + k);
    }
}

// ---------------------------------------------------------------------------
// Kernel 1: sequential LSTM + measurement chain. One block per batch,
// 512 threads. WhhT chunks 0..19 resident in smem (coalesced load+read);
// remaining 12 chunks + WihT prefetched coalesced from global.
// ---------------------------------------------------------------------------
__global__ void __launch_bounds__(NTH, 1) k_seq(
    const float* __restrict__ snapshot, const float* __restrict__ bcv,
    const float* __restrict__ rho, const float* __restrict__ h0,
    const float* __restrict__ c0, const float* __restrict__ bih,
    const float* __restrict__ bhh, const float* __restrict__ Wp,
    const float* __restrict__ bp, float* __restrict__ bv_out)
{
    extern __shared__ float sm[];
    const int b = blockIdx.x;
    const int tid = threadIdx.x;
    const int lane = tid & 31;
    const int wid = tid >> 5;

    float2* s_psi0 = (float2*)(sm + F_PSI0);
    float2* s_exch = (float2*)(sm + F_EXCH);
    float*  s_g    = sm + F_G;
    float*  s_bsum = sm + F_BSUM;
    float*  s_h    = sm + F_H;
    float*  s_c    = sm + F_C;
    float*  s_x    = sm + F_X;
    float*  s_amps = sm + F_AMPS;
    float*  s_log  = sm + F_LOG;
    float*  s_red  = sm + F_RED;
    float*  s_norm = sm + F_NORM;
    ulonglong2* s_whh = (ulonglong2*)(sm + F_WHHS);

    // ---- one-time loads ----
    // WhhT chunks 0..19 into smem, same [k][r] layout (coalesced load + read)
    {
        for (int i = tid; i < SMEM_CHUNKS * 512; i += NTH)
            s_whh[i] = g_WhhT[i];
    }
    // Wp into smem, row pad to 132 floats (33 chunks)
    {
        float4* dst = (float4*)(sm + F_WP);
        const float4* src = (const float4*)Wp;
        for (int i = tid; i < 27 * 32; i += NTH) {
            int row = i >> 5, c4 = i & 31;
            dst[row * 33 + c4] = __ldg(src + i);
        }
    }
    s_bsum[tid] = __ldg(bih + tid) + __ldg(bhh + tid);
    s_psi0[tid] = make_float2(rho[b * 1024 + tid], rho[b * 1024 + 512 + tid]);
    if (tid < 128) { s_h[tid] = h0[b * H + tid]; s_c[tid] = c0[b * H + tid]; }
    if (tid < 9)  s_x[tid] = snapshot[b * NQ + tid];
    if (tid >= 9 && tid < 36) s_x[tid] = bcv[b * 27 + tid - 9];
    __syncthreads();

    // nn0 = ||psi0||^2  (psi0 is NOT normalized in the reference)
    {
        float2 v = s_psi0[tid];
        float nn = v.x * v.x + v.y * v.y;
        #pragma unroll
        for (int off = 16; off; off >>= 1) nn += __shfl_xor_sync(0xffffffffu, nn, off);
        if (lane == 0) s_red[wid * 12] = nn;
        __syncthreads();
        if (tid == 0) {
            float s = 0.0f;
            #pragma unroll
            for (int w = 0; w < 16; w++) s += s_red[w * 12];
            sm[F_NN0] = s;
        }
        __syncthreads();
    }

    for (int t = 0; t < S; t++) {
        // ---- emit rho_q for the current input x ----
        if (tid < 9) {
            int n = tid;
            float sh = s_x[n];
            float p0 = s_x[9 + n * 3 + 0];
            float p1 = s_x[9 + n * 3 + 1];
            float p2 = s_x[9 + n * 3 + 2];
            float2* m = &g_rhoq[(t * B + b) * NQ * 4 + n * 4];
            m[0] = make_float2(0.5f * (1.0f + 3.0f * sh * p2), 0.0f);
            m[1] = make_float2(1.5f * sh * p0, -1.5f * sh * p1);
            m[2] = make_float2(1.5f * sh * p0,  1.5f * sh * p1);
            m[3] = make_float2(0.5f * (1.0f - 3.0f * sh * p2), 0.0f);
        }
        if (t == S - 1) break;

        // ---- LSTM gates: one row per thread ----
        {
            const int r = tid;
            unsigned long long a01 = 0ull, a23 = 0ull, b01 = 0ull, b23 = 0ull;
            const ulonglong2* h2 = (const ulonglong2*)s_h;
            const ulonglong2* x2 = (const ulonglong2*)s_x;

            // phase 1: issue the 21 coalesced global loads (MLP)
            ulonglong2 wg[12 + 9];
            #pragma unroll
            for (int k = 0; k < 12; k++)
                wg[k] = __ldg(g_WhhT + ((SMEM_CHUNKS + k) << 9) + r);
            #pragma unroll
            for (int k = 0; k < 9; k++)
                wg[12 + k] = __ldg(g_WihT + (k << 9) + r);

            // phase 2: smem WhhT chunks 0..19 (hides global latency)
            #pragma unroll
            for (int k = 0; k < SMEM_CHUNKS; k++) {
                ulonglong2 w = s_whh[(k << 9) + r];
                ulonglong2 hv = h2[k];
                if (k & 1) { fma2(b01, w.x, hv.x); fma2(b23, w.y, hv.y); }
                else       { fma2(a01, w.x, hv.x); fma2(a23, w.y, hv.y); }
            }
            // phase 3: consume global registers
            #pragma unroll
            for (int k = 0; k < 12; k++) {
                ulonglong2 hv = h2[SMEM_CHUNKS + k];
                if (k & 1) { fma2(b01, wg[k].x, hv.x); fma2(b23, wg[k].y, hv.y); }
                else       { fma2(a01, wg[k].x, hv.x); fma2(a23, wg[k].y, hv.y); }
            }
            #pragma unroll
            for (int k = 0; k < 9; k++) {
                ulonglong2 xv = x2[k];
                if (k & 1) { fma2(b01, wg[12 + k].x, xv.x); fma2(b23, wg[12 + k].y, xv.y); }
                else       { fma2(a01, wg[12 + k].x, xv.x); fma2(a23, wg[12 + k].y, xv.y); }
            }
            float2 fa = unpack2(a01), fb = unpack2(a23);
            float2 fc = unpack2(b01), fd = unpack2(b23);
            s_g[r] = ((fa.x + fa.y) + (fb.x + fb.y))
                   + ((fc.x + fc.y) + (fd.x + fd.y)) + s_bsum[r];
        }
        __syncthreads();

        // ---- elementwise LSTM update ----
        if (tid < 128) {
            float ig = sigmoidf_(s_g[tid]);
            float fg = sigmoidf_(s_g[128 + tid]);
            float gg = tanhf(s_g[256 + tid]);
            float og = sigmoidf_(s_g[384 + tid]);
            float c = fg * s_c[tid] + ig * gg;
            s_c[tid] = c;
            s_h[tid] = og * tanhf(c);
        }
        __syncthreads();

        // ---- projector logits: 27 outputs x 16 threads ----
        // ALL threads execute the shuffles (clamped index) to keep full-warp
        // participation in __shfl_down_sync.
        {
            int grp = tid >> 4, l = tid & 15;
            int grpc = grp < 27 ? grp : 26;
            const float4* wr = (const float4*)(sm + F_WP + grpc * 132) + l * 2;
            const float4* h4 = (const float4*)s_h + l * 2;
            float4 w0 = wr[0], w1 = wr[1];
            float4 v0 = h4[0], v1 = h4[1];
            float p = w0.x * v0.x + w0.y * v0.y + w0.z * v0.z + w0.w * v0.w
                    + w1.x * v1.x + w1.y * v1.y + w1.z * v1.z + w1.w * v1.w;
            p += __shfl_down_sync(0xffffffffu, p, 8, 16);
            p += __shfl_down_sync(0xffffffffu, p, 4, 16);
            p += __shfl_down_sync(0xffffffffu, p, 2, 16);
            p += __shfl_down_sync(0xffffffffu, p, 1, 16);
            if (l == 0 && grp < 27) s_log[grp] = p + __ldg(bp + grp);
        }
        __syncthreads();
        if (tid < 9) {
            float l0 = s_log[tid * 3], l1 = s_log[tid * 3 + 1], l2 = s_log[tid * 3 + 2];
            float m = fmaxf(l0, fmaxf(l1, l2));
            float e0 = expf(l0 - m), e1 = expf(l1 - m), e2 = expf(l2 - m);
            float inv = 1.0f / (e0 + e1 + e2);
            s_amps[tid * 3 + 0] = sqrtf(e0 * inv);
            s_amps[tid * 3 + 1] = sqrtf(e1 * inv);
            s_amps[tid * 3 + 2] = sqrtf(e2 * inv);
        }
        __syncthreads();

        // ---- 9 collapses, psi in registers, unnormalized with deferred norms ----
        {
            float2 v = s_psi0[tid];
            float nrm[9];
            #pragma unroll
            for (int q = 0; q < 9; q++) {
                float a1 = s_amps[q * 3], a2 = s_amps[q * 3 + 1], a3 = s_amps[q * 3 + 2];
                float an  = sqrtf(a1 * a1 + a2 * a2 + a3 * a3);
                float apn = a3 + an;
                float inv2 = 1.0f / (2.0f * an * apn);
                float t00 = apn * apn * inv2;
                float t11 = (a1 * a1 + a2 * a2) * inv2;
                float cr  = apn * a1 * inv2;
                float ci  = apn * a2 * inv2;
                const int p = 8 - q;
                const int d = 1 << p;
                float2 w;
                if (p >= 5) {
                    float2* buf = s_exch + (q & 1) * 512;
                    buf[tid] = v;
                    __syncthreads();
                    w = buf[tid ^ d];
                } else {
                    w.x = __shfl_xor_sync(0xffffffffu, v.x, d);
                    w.y = __shfl_xor_sync(0xffffffffu, v.y, d);
                }
                bool hi = (tid & d) != 0;
                float td = hi ? t11 : t00;
                float sg = hi ? -ci : ci;
                float2 nv;
                nv.x = td * v.x + cr * w.x + sg * w.y;
                nv.y = td * v.y + cr * w.y - sg * w.x;
                v = nv;
                nrm[q] = v.x * v.x + v.y * v.y;
            }
            // batched reduction of 9 norms
            #pragma unroll
            for (int q = 0; q < 9; q++) {
                float val = nrm[q];
                #pragma unroll
                for (int off = 16; off; off >>= 1)
                    val += __shfl_xor_sync(0xffffffffu, val, off);
                if (lane == 0) s_red[wid * 12 + q] = val;
            }
            __syncthreads();
            if (tid < 9) {
                float ssum = 0.0f;
                #pragma unroll
                for (int w = 0; w < 16; w++) ssum += s_red[w * 12 + tid];
                s_norm[tid] = ssum;
            }
            __syncthreads();
        }

        // ---- build next input x = [snap(9), amps(27)] ----
        // psi0 is UNNORMALIZED: s_0 = 2*||P0 psi0||^2 - ||psi0||^2.
        // For q >= 1 the chain is normalized: s_q = 2*nrm[q]/nrm[q-1] - 1.
        if (tid < 9) {
            float sq;
            if (tid == 0) sq = 2.0f * s_norm[0] - sm[F_NN0];
            else          sq = 2.0f * s_norm[tid] / s_norm[tid - 1] - 1.0f;
            s_x[tid] = sq;
        } else if (tid < 36) {
            s_x[tid] = s_amps[tid - 9];
        }
        if (t == S - 2 && bv_out != nullptr && tid < 27)
            bv_out[b * 27 + tid] = s_amps[tid];
        __syncthreads();
    }
}

// ---------------------------------------------------------------------------
// Kernel 2: partial Kronecker products per (b, t)
// ---------------------------------------------------------------------------
__global__ void __launch_bounds__(256) k_kron()
{
    int bi = blockIdx.x;            // 0 .. S*B-1
    int b = bi >> 4;
    int t = bi & 15;
    __shared__ float2 s_m[NQ * 4];
    int tid = threadIdx.x;
    if (tid < NQ * 4) s_m[tid] = g_rhoq[(t * B + b) * NQ * 4 + tid];
    __syncthreads();

    // A: qubits 0..3 -> 16x16
    {
        int r = tid >> 4, c = tid & 15;
        float2 v = s_m[0 * 4 + ((r >> 3) & 1) * 2 + ((c >> 3) & 1)];
        #pragma unroll
        for (int q = 1; q < 4; q++) {
            float2 m = s_m[q * 4 + ((r >> (3 - q)) & 1) * 2 + ((c >> (3 - q)) & 1)];
            v = cmul(v, m);
        }
        g_A[(b * S + t) * 256 + tid] = v;
    }
    // B: qubits 4..8 -> 32x32 (4 elems per thread)
    #pragma unroll
    for (int j = 0; j < 4; j++) {
        int lp = tid + j * 256;
        int r = lp >> 5, c = lp & 31;
        float2 v = s_m[4 * 4 + ((r >> 4) & 1) * 2 + ((c >> 4) & 1)];
        #pragma unroll
        for (int q = 5; q < 9; q++) {
            float2 m = s_m[q * 4 + ((r >> (8 - q)) & 1) * 2 + ((c >> (8 - q)) & 1)];
            v = cmul(v, m);
        }
        g_Bm[(b * S + t) * 1024 + lp] = v;
    }
}

// ---------------------------------------------------------------------------
// Kernel 3: acc[b][hp][lp] = (1/S) * sum_t A_t[hp] * B_t[lp], packed FFMA2.
// A pre-packed in smem as (ax, ax, -ay, ay): complex MAC = 2 x fma2.
// out layout: [B][2][512][512]  (real plane, imag plane)
// ---------------------------------------------------------------------------
__global__ void __launch_bounds__(256) k_acc(float* __restrict__ out)
{
    int b = blockIdx.z;
    int hpBase = blockIdx.x * 16;
    int tx = threadIdx.x;                 // 0..31 -> lo_c
    int ty = threadIdx.y;                 // 0..7
    int lo_r = blockIdx.y * 8 + ty;
    int lp = lo_r * 32 + tx;
    __shared__ __align__(16) float A_s[S][16][4];   // (ax, ax, -ay, ay)
    int tid = ty * 32 + tx;
    {
        int t = tid >> 4, j = tid & 15;
        float2 a = g_A[(b * S + t) * 256 + hpBase + j];
        A_s[t][j][0] = a.x; A_s[t][j][1] = a.x;
        A_s[t][j][2] = -a.y; A_s[t][j][3] = a.y;
    }
    __syncthreads();

    unsigned long long acc[16];
    #pragma unroll
    for (int j = 0; j < 16; j++) acc[j] = 0ull;

    #pragma unroll
    for (int t = 0; t < S; t++) {
        float2 bv = g_Bm[(b * S + t) * 1024 + lp];
        unsigned long long b01 = pack2(bv.x, bv.y);   // (bx, by)
        unsigned long long b10 = pack2(bv.y, bv.x);   // (by, bx)
        #pragma unroll
        for (int j = 0; j < 16; j++) {
            ulonglong2 a = *(const ulonglong2*)A_s[t][j]; // (ax,ax), (-ay,ay)
            fma2(acc[j], a.x, b01);   // re += ax*bx,  im += ax*by
            fma2(acc[j], a.y, b10);   // re += -ay*by, im += ay*bx
        }
    }

    const float sc = 1.0f / (float)S;
    float* outr = out + (size_t)b * 2 * D * D;
    float* outi = outr + D * D;
    #pragma unroll
    for (int j = 0; j < 16; j++) {
        float2 v = unpack2(acc[j]);
        int hp = hpBase + j;
        int row = (hp >> 4) * 32 + lo_r;
        int col = (hp & 15) * 32 + tx;
        outr[row * D + col] = v.x * sc;
        outi[row * D + col] = v.y * sc;
    }
}

// ---------------------------------------------------------------------------
extern "C" void kernel_launch(void* const* d_in, const int* in_sizes, int n_in,
                              void* d_out, int out_size)
{
    const float* snapshot = (const float*)d_in[0];
    const float* bcv      = (const float*)d_in[1];
    const float* rho      = (const float*)d_in[2];
    const float* h0       = (const float*)d_in[3];
    const float* c0       = (const float*)d_in[4];
    const float* Wih      = (const float*)d_in[5];
    const float* Whh      = (const float*)d_in[6];
    const float* bih      = (const float*)d_in[7];
    const float* bhh      = (const float*)d_in[8];
    const float* Wp       = (const float*)d_in[9];
    const float* bp       = (const float*)d_in[10];

    float* out = (float*)d_out;
    const int main_elems = 2 * B * D * D;
    const int bv_elems = B * NQ * KK;
    float* bv_out = (out_size >= main_elems + bv_elems) ? (out + main_elems) : nullptr;

    // Unconditional (no static guards). Host API, enqueues nothing — capture-safe.
    cudaFuncSetAttribute(k_seq, cudaFuncAttributeMaxDynamicSharedMemorySize,
                         SMEM_FLOATS * (int)sizeof(float));

    k_transpose<<<82, 256>>>(Whh, Wih);
    k_seq<<<B, NTH, SMEM_FLOATS * sizeof(float)>>>(
        snapshot, bcv, rho, h0, c0, bih, bhh, Wp, bp, bv_out);
    k_kron<<<S * B, 256>>>();
    dim3 g3(16, 4, B);
    k_acc<<<g3, dim3(32, 8)>>>(out);
}